// round 12
// baseline (speedup 1.0000x reference)
#include <cuda_runtime.h>
#include <math.h>

typedef unsigned long long ULL;

// ---------------------------------------------------------------------------
// B=16, dim=48, hid=16, C=8, H=W=256, HW=65536. Total pixels = 1,048,576.
// kA: no-smem, 2 px/thread (amortize the 384 LDCU weight loads), packed gelu.
// kB: proven 42.7us version (at LTS ceiling), untouched.
// ---------------------------------------------------------------------------
#define HW 65536
#define NB 16

// Scratch (allocation-free rule: __device__ globals). 33.5 MB each.
__device__ __align__(16) float g_n [NB * 8 * HW];   // planar (B, C, HW) — LN'd x2
__device__ __align__(16) float g_x1[NB * HW * 8];   // (B, HW, C) — gate branch

// Weights in constant memory (compile-time-indexed -> LDCU uniform port)
__constant__ ULL   cW1p[384];   // W1 (48,16) as pairs [k*8 + j2]
__constant__ ULL   cW2p[192];   // W2 (8,48)  as pairs [c*24 + d2]
__constant__ float cdw[72];     // dw_w (8,1,3,3)
__constant__ float cpw[64];     // pw_w (8,8)
__constant__ float cb1[16];
__constant__ float cgam[8], cbet[8], cdwb[8], cpwb[8];
__constant__ ULL   cb2p[24];    // b2 (48) as pairs

// ---- packed f32x2 helpers (sm_103a) ----
__device__ __forceinline__ ULL pk(float a, float b) {
    ULL r; asm("mov.b64 %0,{%1,%2};" : "=l"(r) : "f"(a), "f"(b)); return r;
}
__device__ __forceinline__ void upk(ULL v, float& a, float& b) {
    asm("mov.b64 {%0,%1},%2;" : "=f"(a), "=f"(b) : "l"(v));
}
__device__ __forceinline__ ULL f2fma(ULL a, ULL b, ULL c) {
    ULL d; asm("fma.rn.f32x2 %0,%1,%2,%3;" : "=l"(d) : "l"(a), "l"(b), "l"(c)); return d;
}
__device__ __forceinline__ ULL f2mul(ULL a, ULL b) {
    ULL d; asm("mul.rn.f32x2 %0,%1,%2;" : "=l"(d) : "l"(a), "l"(b)); return d;
}
__device__ __forceinline__ ULL f2add(ULL a, ULL b) {
    ULL d; asm("add.rn.f32x2 %0,%1,%2;" : "=l"(d) : "l"(a), "l"(b)); return d;
}
__device__ __forceinline__ float rcp_fast(float a) {
    float r; asm("rcp.approx.f32 %0,%1;" : "=f"(r) : "f"(a)); return r;
}
__device__ __forceinline__ float ex2_fast(float a) {
    float r; asm("ex2.approx.f32 %0,%1;" : "=f"(r) : "f"(a)); return r;
}

// Packed double-lane GELU (A&S 7.1.26, |abs err| <= 1.5e-7 per erf).
// Verified rel_err 4.47e-7 in R11 bench.
__device__ __forceinline__ ULL gelu2(ULL v) {
    const ULL ONE  = 0x3f8000003f800000ULL;            // (1.0f, 1.0f)
    const ULL HALF = 0x3f0000003f000000ULL;            // (0.5f, 0.5f)
    ULL x  = f2mul(v, pk(0.70710678f, 0.70710678f));   // x = v/sqrt(2)
    ULL ax = x & 0x7fffffff7fffffffULL;                // |x|
    ULL dn = f2fma(pk(0.3275911f, 0.3275911f), ax, ONE);
    float d0, d1; upk(dn, d0, d1);
    ULL t  = pk(rcp_fast(d0), rcp_fast(d1));
    ULL q = pk(-1.061405429f, -1.061405429f);
    q = f2fma(q, t, pk( 1.453152027f,  1.453152027f));
    q = f2fma(q, t, pk(-1.421413741f, -1.421413741f));
    q = f2fma(q, t, pk( 0.284496736f,  0.284496736f));
    q = f2fma(q, t, pk(-0.254829592f, -0.254829592f));
    q = f2mul(q, t);
    ULL xx = f2mul(x, x);
    ULL ea = f2mul(xx, pk(-1.4426950408f, -1.4426950408f));
    float e0, e1; upk(ea, e0, e1);
    ULL e  = pk(ex2_fast(e0), ex2_fast(e1));
    ULL er = f2fma(q, e, ONE);                          // erf(|x|) >= 0
    er = er | (v & 0x8000000080000000ULL);              // copysign from v
    return f2mul(v, f2fma(er, HALF, HALF));             // 0.5*v*(1+erf)
}

// per-pixel epilogue: bias+double gelu, x1 store, LN store
__device__ __forceinline__ void epiA(const ULL* acc, size_t P) {
    ULL hh[8];
#pragma unroll
    for (int j = 0; j < 8; j++) {
        ULL z = f2add(acc[j], pk(cb1[2 * j], cb1[2 * j + 1]));
        hh[j] = gelu2(gelu2(z));
    }

    ulonglong2* x1o = (ulonglong2*)g_x1 + P * 2;
    x1o[0] = make_ulonglong2(hh[0], hh[1]);
    x1o[1] = make_ulonglong2(hh[2], hh[3]);

    ULL s2 = f2add(f2add(hh[4], hh[5]), f2add(hh[6], hh[7]));
    float sa, sb; upk(s2, sa, sb);
    float m = (sa + sb) * 0.125f;
    ULL mm = pk(-m, -m);
    ULL dj[4];
    ULL vq = 0ULL;
#pragma unroll
    for (int j = 0; j < 4; j++) {
        dj[j] = f2add(hh[4 + j], mm);
        vq = f2fma(dj[j], dj[j], vq);
    }
    float va, vb; upk(vq, va, vb);
    float inv = rsqrtf((va + vb) * 0.125f + 1e-5f);

    size_t b_ = P >> 16, pp = P & 65535;
    float* nb = g_n + (b_ << 19) + pp;
#pragma unroll
    for (int j = 0; j < 4; j++) {
        ULL gi = f2mul(pk(cgam[2 * j], cgam[2 * j + 1]), pk(inv, inv));
        ULL nj = f2fma(dj[j], gi, pk(cbet[2 * j], cbet[2 * j + 1]));
        float n0, n1; upk(nj, n0, n1);
        nb[(size_t)(2 * j)     << 16] = n0;
        nb[(size_t)(2 * j + 1) << 16] = n1;
    }
}

// ---------------------------------------------------------------------------
// Kernel A: 256 threads, 2 px/thread (P, P+256), NO shared memory. The 384
// LDCU weight loads per iteration feed both pixels' FFMA2 streams.
// 2048 blocks of 512 pixels.
// ---------------------------------------------------------------------------
__global__ void __launch_bounds__(256, 3) kA(const float* __restrict__ x) {
    int t = threadIdx.x;
    size_t P0 = (size_t)blockIdx.x * 512 + (size_t)t;   // px0
    size_t P1 = P0 + 256;                                // px1
    const float4* xp0 = (const float4*)(x + P0 * 48);
    const float4* xp1 = (const float4*)(x + P1 * 48);

    ULL a0[8], a1[8];
#pragma unroll
    for (int j = 0; j < 8; j++) { a0[j] = 0ULL; a1[j] = 0ULL; }

#pragma unroll
    for (int f = 0; f < 12; f++) {
        float4 v0 = __ldg(xp0 + f);
        float4 v1 = __ldg(xp1 + f);
        float k0[4] = {v0.x, v0.y, v0.z, v0.w};
        float k1[4] = {v1.x, v1.y, v1.z, v1.w};
#pragma unroll
        for (int q = 0; q < 4; q++) {
            int k = f * 4 + q;
            ULL bx0 = pk(k0[q], k0[q]);
            ULL bx1 = pk(k1[q], k1[q]);
#pragma unroll
            for (int j = 0; j < 8; j++) {
                ULL w = cW1p[k * 8 + j];     // one LDCU, two FFMA2
                a0[j] = f2fma(bx0, w, a0[j]);
                a1[j] = f2fma(bx1, w, a1[j]);
            }
        }
    }

    epiA(a0, P0);
    epiA(a1, P1);
}

// ---------------------------------------------------------------------------
// Kernel B (proven, constant weights): one block = one (b,h) row;
// 128 threads, pixel pair (2t, 2t+1) packed in f32x2 lanes.
// ---------------------------------------------------------------------------
__global__ void __launch_bounds__(128) kB(float* __restrict__ out) {
    __shared__ __align__(16) float ns[8][3][264];   // halo cols 0 and 257 zeroed

    int t = threadIdx.x;
    int b_ = blockIdx.x >> 8;
    int h  = blockIdx.x & 255;
    int w0 = 2 * t;

    // prefetch x1 (DRAM latency hidden behind smem fill + conv)
    size_t P0 = ((size_t)b_ << 16) + ((size_t)h << 8) + (size_t)w0;
    const float4* x1v = (const float4*)(g_x1 + P0 * 8);
    float4 XA = x1v[0], XB = x1v[1], XC = x1v[2], XD = x1v[3];

    const float* nbase = g_n + ((size_t)b_ << 19);
#pragma unroll
    for (int c = 0; c < 8; c++) {
#pragma unroll
        for (int r = 0; r < 3; r++) {
            int hs = h + r - 1;
            float2 v = make_float2(0.f, 0.f);
            if ((unsigned)hs < 256u)
                v = ((const float2*)(nbase + ((size_t)c << 16) + ((size_t)hs << 8)))[t];
            ns[c][r][1 + w0] = v.x;
            ns[c][r][2 + w0] = v.y;
        }
    }
    if (t == 0) {
#pragma unroll
        for (int c = 0; c < 8; c++)
#pragma unroll
            for (int r = 0; r < 3; r++) { ns[c][r][0] = 0.f; ns[c][r][257] = 0.f; }
    }
    __syncthreads();

    // depthwise 3x3 (SAME)
    ULL spp[8], ncp[8];
#pragma unroll
    for (int c = 0; c < 8; c++) {
        ULL acc = 0ULL, center = 0ULL;
#pragma unroll
        for (int r = 0; r < 3; r++) {
            ULL v01 = *(const ULL*)&ns[c][r][w0];       // (w0-1, w0)
            ULL v23 = *(const ULL*)&ns[c][r][w0 + 2];   // (w0+1, w0+2)
            ULL v12 = (v01 >> 32) | (v23 << 32);        // (w0,   w0+1)
            float wa = cdw[c * 9 + r * 3 + 0];
            float wb = cdw[c * 9 + r * 3 + 1];
            float wc = cdw[c * 9 + r * 3 + 2];
            acc = f2fma(v01, pk(wa, wa), acc);
            acc = f2fma(v12, pk(wb, wb), acc);
            acc = f2fma(v23, pk(wc, wc), acc);
            if (r == 1) center = v12;
        }
        spp[c] = f2add(acc, pk(cdwb[c], cdwb[c]));
        ncp[c] = center;
    }

    // pointwise 1x1
    ULL chp[8];
#pragma unroll
    for (int c = 0; c < 8; c++) {
        ULL a = pk(cpwb[c], cpwb[c]);
#pragma unroll
        for (int c2 = 0; c2 < 8; c2++) {
            float w = cpw[c * 8 + c2];
            a = f2fma(ncp[c2], pk(w, w), a);
        }
        chp[c] = a;
    }

    // gate: g = x1 * sp * ch   (lanes = the two pixels)
    float x10[8] = {XA.x, XA.y, XA.z, XA.w, XB.x, XB.y, XB.z, XB.w};
    float x11[8] = {XC.x, XC.y, XC.z, XC.w, XD.x, XD.y, XD.z, XD.w};
    ULL gp[8];
#pragma unroll
    for (int c = 0; c < 8; c++)
        gp[c] = f2mul(pk(x10[c], x11[c]), f2mul(spp[c], chp[c]));

    // GEMM2 in 4 quarters of 12 outputs (lower live regs)
    float* ob = out + (((size_t)b_ * 48) << 16) + ((size_t)h << 8) + (size_t)w0;
#pragma unroll
    for (int q = 0; q < 4; q++) {
        ULL o0[6], o1[6];
#pragma unroll
        for (int j = 0; j < 6; j++) { o0[j] = cb2p[q * 6 + j]; o1[j] = o0[j]; }
#pragma unroll
        for (int c = 0; c < 8; c++) {
            float g0, g1; upk(gp[c], g0, g1);
            ULL gb0 = pk(g0, g0), gb1 = pk(g1, g1);
#pragma unroll
            for (int j = 0; j < 6; j++) {
                ULL wv = cW2p[c * 24 + q * 6 + j];
                o0[j] = f2fma(gb0, wv, o0[j]);
                o1[j] = f2fma(gb1, wv, o1[j]);
            }
        }
#pragma unroll
        for (int j = 0; j < 6; j++) {
            float p00, p01, p10, p11;
            upk(o0[j], p00, p01);   // px0: d = d0, d0+1
            upk(o1[j], p10, p11);   // px1
            int d0 = q * 12 + 2 * j;
            *((float2*)(ob + ((size_t)d0 << 16)))       = make_float2(p00, p10);
            *((float2*)(ob + ((size_t)(d0 + 1) << 16))) = make_float2(p01, p11);
        }
    }
}

// ---------------------------------------------------------------------------
extern "C" void kernel_launch(void* const* d_in, const int* in_sizes, int n_in,
                              void* d_out, int out_size) {
    const float* x = (const float*)d_in[0];
    float* out = (float*)d_out;

    // weights -> constant memory (async D2D; graph-capturable memcpy nodes)
    cudaMemcpyToSymbolAsync(cW1p, d_in[1], 768 * 4, 0, cudaMemcpyDeviceToDevice);
    cudaMemcpyToSymbolAsync(cb1,  d_in[2], 16 * 4,  0, cudaMemcpyDeviceToDevice);
    cudaMemcpyToSymbolAsync(cgam, d_in[3], 8 * 4,   0, cudaMemcpyDeviceToDevice);
    cudaMemcpyToSymbolAsync(cbet, d_in[4], 8 * 4,   0, cudaMemcpyDeviceToDevice);
    cudaMemcpyToSymbolAsync(cdw,  d_in[5], 72 * 4,  0, cudaMemcpyDeviceToDevice);
    cudaMemcpyToSymbolAsync(cdwb, d_in[6], 8 * 4,   0, cudaMemcpyDeviceToDevice);
    cudaMemcpyToSymbolAsync(cpw,  d_in[7], 64 * 4,  0, cudaMemcpyDeviceToDevice);
    cudaMemcpyToSymbolAsync(cpwb, d_in[8], 8 * 4,   0, cudaMemcpyDeviceToDevice);
    cudaMemcpyToSymbolAsync(cW2p, d_in[9], 384 * 4, 0, cudaMemcpyDeviceToDevice);
    cudaMemcpyToSymbolAsync(cb2p, d_in[10], 48 * 4, 0, cudaMemcpyDeviceToDevice);

    kA<<<2048, 256>>>(x);
    kB<<<4096, 128>>>(out);
}

// round 15
// speedup vs baseline: 1.0198x; 1.0198x over previous
#include <cuda_runtime.h>
#include <math.h>

typedef unsigned long long ULL;

// ---------------------------------------------------------------------------
// B=16, dim=48, hid=16, C=8, H=W=256, HW=65536. Total pixels = 1,048,576.
// kA: 256 thr, 1 px/thread, x staged coalesced into smem (rotation swizzle),
//     LDCU weights, packed gelu2. (R10 kernel + staging; kills the 12.6M
//     L1TEX-wavefront floor of the uncoalesced direct loads.)
// kB: proven 43us version (at LTS ceiling), untouched.
// ---------------------------------------------------------------------------
#define HW 65536
#define NB 16

// Scratch (allocation-free rule: __device__ globals). 33.5 MB each.
__device__ __align__(16) float g_n [NB * 8 * HW];   // planar (B, C, HW) — LN'd x2
__device__ __align__(16) float g_x1[NB * HW * 8];   // (B, HW, C) — gate branch

// Weights in constant memory (compile-time-indexed -> LDCU uniform port)
__constant__ ULL   cW1p[384];   // W1 (48,16) as pairs [k*8 + j2]
__constant__ ULL   cW2p[192];   // W2 (8,48)  as pairs [c*24 + d2]
__constant__ float cdw[72];     // dw_w (8,1,3,3)
__constant__ float cpw[64];     // pw_w (8,8)
__constant__ float cb1[16];
__constant__ float cgam[8], cbet[8], cdwb[8], cpwb[8];
__constant__ ULL   cb2p[24];    // b2 (48) as pairs

// ---- packed f32x2 helpers (sm_103a) ----
__device__ __forceinline__ ULL pk(float a, float b) {
    ULL r; asm("mov.b64 %0,{%1,%2};" : "=l"(r) : "f"(a), "f"(b)); return r;
}
__device__ __forceinline__ void upk(ULL v, float& a, float& b) {
    asm("mov.b64 {%0,%1},%2;" : "=f"(a), "=f"(b) : "l"(v));
}
__device__ __forceinline__ ULL f2fma(ULL a, ULL b, ULL c) {
    ULL d; asm("fma.rn.f32x2 %0,%1,%2,%3;" : "=l"(d) : "l"(a), "l"(b), "l"(c)); return d;
}
__device__ __forceinline__ ULL f2mul(ULL a, ULL b) {
    ULL d; asm("mul.rn.f32x2 %0,%1,%2;" : "=l"(d) : "l"(a), "l"(b)); return d;
}
__device__ __forceinline__ ULL f2add(ULL a, ULL b) {
    ULL d; asm("add.rn.f32x2 %0,%1,%2;" : "=l"(d) : "l"(a), "l"(b)); return d;
}
__device__ __forceinline__ float rcp_fast(float a) {
    float r; asm("rcp.approx.f32 %0,%1;" : "=f"(r) : "f"(a)); return r;
}
__device__ __forceinline__ float ex2_fast(float a) {
    float r; asm("ex2.approx.f32 %0,%1;" : "=f"(r) : "f"(a)); return r;
}

// Packed double-lane GELU (A&S 7.1.26, |abs err| <= 1.5e-7 per erf).
// Verified rel_err 4.47e-7 in R11/R12 benches.
__device__ __forceinline__ ULL gelu2(ULL v) {
    const ULL ONE  = 0x3f8000003f800000ULL;            // (1.0f, 1.0f)
    const ULL HALF = 0x3f0000003f000000ULL;            // (0.5f, 0.5f)
    ULL x  = f2mul(v, pk(0.70710678f, 0.70710678f));   // x = v/sqrt(2)
    ULL ax = x & 0x7fffffff7fffffffULL;                // |x|
    ULL dn = f2fma(pk(0.3275911f, 0.3275911f), ax, ONE);
    float d0, d1; upk(dn, d0, d1);
    ULL t  = pk(rcp_fast(d0), rcp_fast(d1));
    ULL q = pk(-1.061405429f, -1.061405429f);
    q = f2fma(q, t, pk( 1.453152027f,  1.453152027f));
    q = f2fma(q, t, pk(-1.421413741f, -1.421413741f));
    q = f2fma(q, t, pk( 0.284496736f,  0.284496736f));
    q = f2fma(q, t, pk(-0.254829592f, -0.254829592f));
    q = f2mul(q, t);
    ULL xx = f2mul(x, x);
    ULL ea = f2mul(xx, pk(-1.4426950408f, -1.4426950408f));
    float e0, e1; upk(ea, e0, e1);
    ULL e  = pk(ex2_fast(e0), ex2_fast(e1));
    ULL er = f2fma(q, e, ONE);                          // erf(|x|) >= 0
    er = er | (v & 0x8000000080000000ULL);              // copysign from v
    return f2mul(v, f2fma(er, HALF, HALF));             // 0.5*v*(1+erf)
}

// ---------------------------------------------------------------------------
// Kernel A: 256 threads, 1 px/thread. x staged coalesced into 48KB smem with
// the R2-proven rotation swizzle (pixel p's chunk f at slot p*12 + (f+p)%12);
// GEMM1 from smem + LDCU weights; packed gelu2; LN epilogue. 4096 blocks.
// ---------------------------------------------------------------------------
__global__ void __launch_bounds__(256) kA(const float* __restrict__ x) {
    __shared__ __align__(16) float4 xs4[256 * 12];   // 48 KB

    int t = threadIdx.x;
    size_t Pbase = (size_t)blockIdx.x * 256;
    const float4* gx = (const float4*)(x + Pbase * 48);

    // coalesced staging: 3072 float4 by 256 threads = 12 iterations
#pragma unroll
    for (int i = 0; i < 12; i++) {
        int idx = i * 256 + t;          // 0..3071
        int p = idx / 12;
        int f = idx - p * 12;
        int fr = f + p; fr %= 12;
        xs4[p * 12 + fr] = gx[idx];
    }
    __syncthreads();

    // GEMM1: 8 f32x2 accumulators (16 outputs, pairs (h2j, h2j+1))
    ULL acc[8];
#pragma unroll
    for (int j = 0; j < 8; j++) acc[j] = 0ULL;

    int r0 = t % 12;
#pragma unroll
    for (int f = 0; f < 12; f++) {
        int fr = f + r0; if (fr >= 12) fr -= 12;
        float4 v = xs4[t * 12 + fr];
        float kv[4] = {v.x, v.y, v.z, v.w};
#pragma unroll
        for (int q = 0; q < 4; q++) {
            int k = f * 4 + q;
            ULL bx = pk(kv[q], kv[q]);
#pragma unroll
            for (int j = 0; j < 8; j++)
                acc[j] = f2fma(bx, cW1p[k * 8 + j], acc[j]);
        }
    }

    // epilogue: bias + double gelu, fully packed
    size_t P = Pbase + (size_t)t;
    ULL hh[8];
#pragma unroll
    for (int j = 0; j < 8; j++) {
        ULL z = f2add(acc[j], pk(cb1[2 * j], cb1[2 * j + 1]));
        hh[j] = gelu2(gelu2(z));
    }

    // x1 = h[0:8] -> g_x1 (pairs are already contiguous)
    ulonglong2* x1o = (ulonglong2*)g_x1 + P * 2;
    x1o[0] = make_ulonglong2(hh[0], hh[1]);
    x1o[1] = make_ulonglong2(hh[2], hh[3]);

    // layernorm over h[8..15] (pairs hh[4..7])
    ULL s2 = f2add(f2add(hh[4], hh[5]), f2add(hh[6], hh[7]));
    float sa, sb; upk(s2, sa, sb);
    float m = (sa + sb) * 0.125f;
    ULL mm = pk(-m, -m);
    ULL dj[4];
    ULL vq = 0ULL;
#pragma unroll
    for (int j = 0; j < 4; j++) {
        dj[j] = f2add(hh[4 + j], mm);
        vq = f2fma(dj[j], dj[j], vq);
    }
    float va, vb; upk(vq, va, vb);
    float inv = rsqrtf((va + vb) * 0.125f + 1e-5f);

    size_t b_ = P >> 16, pp = P & 65535;
    float* nb = g_n + (b_ << 19) + pp;
#pragma unroll
    for (int j = 0; j < 4; j++) {
        ULL gi = f2mul(pk(cgam[2 * j], cgam[2 * j + 1]), pk(inv, inv));
        ULL nj = f2fma(dj[j], gi, pk(cbet[2 * j], cbet[2 * j + 1]));
        float n0, n1; upk(nj, n0, n1);
        nb[(size_t)(2 * j)     << 16] = n0;
        nb[(size_t)(2 * j + 1) << 16] = n1;
    }
}

// ---------------------------------------------------------------------------
// Kernel B (proven, constant weights): one block = one (b,h) row;
// 128 threads, pixel pair (2t, 2t+1) packed in f32x2 lanes.
// ---------------------------------------------------------------------------
__global__ void __launch_bounds__(128) kB(float* __restrict__ out) {
    __shared__ __align__(16) float ns[8][3][264];   // halo cols 0 and 257 zeroed

    int t = threadIdx.x;
    int b_ = blockIdx.x >> 8;
    int h  = blockIdx.x & 255;
    int w0 = 2 * t;

    // prefetch x1 (DRAM latency hidden behind smem fill + conv)
    size_t P0 = ((size_t)b_ << 16) + ((size_t)h << 8) + (size_t)w0;
    const float4* x1v = (const float4*)(g_x1 + P0 * 8);
    float4 XA = x1v[0], XB = x1v[1], XC = x1v[2], XD = x1v[3];

    const float* nbase = g_n + ((size_t)b_ << 19);
#pragma unroll
    for (int c = 0; c < 8; c++) {
#pragma unroll
        for (int r = 0; r < 3; r++) {
            int hs = h + r - 1;
            float2 v = make_float2(0.f, 0.f);
            if ((unsigned)hs < 256u)
                v = ((const float2*)(nbase + ((size_t)c << 16) + ((size_t)hs << 8)))[t];
            ns[c][r][1 + w0] = v.x;
            ns[c][r][2 + w0] = v.y;
        }
    }
    if (t == 0) {
#pragma unroll
        for (int c = 0; c < 8; c++)
#pragma unroll
            for (int r = 0; r < 3; r++) { ns[c][r][0] = 0.f; ns[c][r][257] = 0.f; }
    }
    __syncthreads();

    // depthwise 3x3 (SAME)
    ULL spp[8], ncp[8];
#pragma unroll
    for (int c = 0; c < 8; c++) {
        ULL acc = 0ULL, center = 0ULL;
#pragma unroll
        for (int r = 0; r < 3; r++) {
            ULL v01 = *(const ULL*)&ns[c][r][w0];       // (w0-1, w0)
            ULL v23 = *(const ULL*)&ns[c][r][w0 + 2];   // (w0+1, w0+2)
            ULL v12 = (v01 >> 32) | (v23 << 32);        // (w0,   w0+1)
            float wa = cdw[c * 9 + r * 3 + 0];
            float wb = cdw[c * 9 + r * 3 + 1];
            float wc = cdw[c * 9 + r * 3 + 2];
            acc = f2fma(v01, pk(wa, wa), acc);
            acc = f2fma(v12, pk(wb, wb), acc);
            acc = f2fma(v23, pk(wc, wc), acc);
            if (r == 1) center = v12;
        }
        spp[c] = f2add(acc, pk(cdwb[c], cdwb[c]));
        ncp[c] = center;
    }

    // pointwise 1x1
    ULL chp[8];
#pragma unroll
    for (int c = 0; c < 8; c++) {
        ULL a = pk(cpwb[c], cpwb[c]);
#pragma unroll
        for (int c2 = 0; c2 < 8; c2++) {
            float w = cpw[c * 8 + c2];
            a = f2fma(ncp[c2], pk(w, w), a);
        }
        chp[c] = a;
    }

    // gate: g = x1 * sp * ch   (lanes = the two pixels)
    float x10[8] = {XA.x, XA.y, XA.z, XA.w, XB.x, XB.y, XB.z, XB.w};
    float x11[8] = {XC.x, XC.y, XC.z, XC.w, XD.x, XD.y, XD.z, XD.w};
    ULL gp[8];
#pragma unroll
    for (int c = 0; c < 8; c++)
        gp[c] = f2mul(pk(x10[c], x11[c]), f2mul(spp[c], chp[c]));

    // GEMM2 in 4 quarters of 12 outputs (lower live regs)
    float* ob = out + (((size_t)b_ * 48) << 16) + ((size_t)h << 8) + (size_t)w0;
#pragma unroll
    for (int q = 0; q < 4; q++) {
        ULL o0[6], o1[6];
#pragma unroll
        for (int j = 0; j < 6; j++) { o0[j] = cb2p[q * 6 + j]; o1[j] = o0[j]; }
#pragma unroll
        for (int c = 0; c < 8; c++) {
            float g0, g1; upk(gp[c], g0, g1);
            ULL gb0 = pk(g0, g0), gb1 = pk(g1, g1);
#pragma unroll
            for (int j = 0; j < 6; j++) {
                ULL wv = cW2p[c * 24 + q * 6 + j];
                o0[j] = f2fma(gb0, wv, o0[j]);
                o1[j] = f2fma(gb1, wv, o1[j]);
            }
        }
#pragma unroll
        for (int j = 0; j < 6; j++) {
            float p00, p01, p10, p11;
            upk(o0[j], p00, p01);   // px0: d = d0, d0+1
            upk(o1[j], p10, p11);   // px1
            int d0 = q * 12 + 2 * j;
            *((float2*)(ob + ((size_t)d0 << 16)))       = make_float2(p00, p10);
            *((float2*)(ob + ((size_t)(d0 + 1) << 16))) = make_float2(p01, p11);
        }
    }
}

// ---------------------------------------------------------------------------
extern "C" void kernel_launch(void* const* d_in, const int* in_sizes, int n_in,
                              void* d_out, int out_size) {
    const float* x = (const float*)d_in[0];
    float* out = (float*)d_out;

    // weights -> constant memory (async D2D; graph-capturable memcpy nodes)
    cudaMemcpyToSymbolAsync(cW1p, d_in[1], 768 * 4, 0, cudaMemcpyDeviceToDevice);
    cudaMemcpyToSymbolAsync(cb1,  d_in[2], 16 * 4,  0, cudaMemcpyDeviceToDevice);
    cudaMemcpyToSymbolAsync(cgam, d_in[3], 8 * 4,   0, cudaMemcpyDeviceToDevice);
    cudaMemcpyToSymbolAsync(cbet, d_in[4], 8 * 4,   0, cudaMemcpyDeviceToDevice);
    cudaMemcpyToSymbolAsync(cdw,  d_in[5], 72 * 4,  0, cudaMemcpyDeviceToDevice);
    cudaMemcpyToSymbolAsync(cdwb, d_in[6], 8 * 4,   0, cudaMemcpyDeviceToDevice);
    cudaMemcpyToSymbolAsync(cpw,  d_in[7], 64 * 4,  0, cudaMemcpyDeviceToDevice);
    cudaMemcpyToSymbolAsync(cpwb, d_in[8], 8 * 4,   0, cudaMemcpyDeviceToDevice);
    cudaMemcpyToSymbolAsync(cW2p, d_in[9], 384 * 4, 0, cudaMemcpyDeviceToDevice);
    cudaMemcpyToSymbolAsync(cb2p, d_in[10], 48 * 4, 0, cudaMemcpyDeviceToDevice);

    kA<<<4096, 256>>>(x);
    kB<<<4096, 128>>>(out);
}